// round 13
// baseline (speedup 1.0000x reference)
#include <cuda_runtime.h>
#include <cuda_bf16.h>
#include <stdint.h>

#define SQn 2048
#define HQn 32
#define HKVn 8
#define Dn 128
#define WINn 512
#define QPn 16               /* q positions per CTA */
#define QTn 64               /* rows per CTA = QPn * 4 heads */
#define KTn 128
#define NQBn 128             /* q blocks = SQn / QPn */
#define NCTAn 2048
#define SPn 640              /* gmem strip pitch (f32) */
#define PQn 136              /* bf16 tile pitch: 272B rows -> LDSM conflict-free */
#define SCALEf 0.088388347648318447f
#define CAPf 30.0f
#define KXf (SCALEf / CAPf)
#define C3f (-0.33333334f)
#define C5f (0.13333333f)
#define C7f (-0.05396825f)

// ---- smem layout (bytes) ----
#define O_QH 0               /* 64*136*2 = 17408 */
#define O_QL 17408
#define O_KS(s) (34816 + (s) * 69632)      /* stage s: KH */
#define O_KSL(s) (O_KS(s) + 34816)         /* stage s: KL */
#define O_SUMS 174080        /* 64 f32 */
#define SMEM_SZ 174336

#define KVELEMS ((size_t)2 * SQn * HKVn * Dn)

__device__ float g_strip[(size_t)NCTAn * QTn * SPn];   // L2-resident scratch
__device__ __nv_bfloat16 gKH[KVELEMS];
__device__ __nv_bfloat16 gKL[KVELEMS];
__device__ __nv_bfloat16 gVH[KVELEMS];
__device__ __nv_bfloat16 gVL[KVELEMS];

__device__ __forceinline__ void ldsm4(uint32_t a, uint32_t r[4]) {
  asm volatile("ldmatrix.sync.aligned.m8n8.x4.shared.b16 {%0,%1,%2,%3}, [%4];"
               : "=r"(r[0]), "=r"(r[1]), "=r"(r[2]), "=r"(r[3]) : "r"(a));
}
__device__ __forceinline__ void ldsm4t(uint32_t a, uint32_t r[4]) {
  asm volatile("ldmatrix.sync.aligned.m8n8.x4.trans.shared.b16 {%0,%1,%2,%3}, [%4];"
               : "=r"(r[0]), "=r"(r[1]), "=r"(r[2]), "=r"(r[3]) : "r"(a));
}
__device__ __forceinline__ void mma16816(float c[4], const uint32_t a[4],
                                         uint32_t b0, uint32_t b1) {
  asm volatile(
      "mma.sync.aligned.m16n8k16.row.col.f32.bf16.bf16.f32 "
      "{%0,%1,%2,%3},{%4,%5,%6,%7},{%8,%9},{%0,%1,%2,%3};"
      : "+f"(c[0]), "+f"(c[1]), "+f"(c[2]), "+f"(c[3])
      : "r"(a[0]), "r"(a[1]), "r"(a[2]), "r"(a[3]), "r"(b0), "r"(b1));
}
__device__ __forceinline__ uint32_t s2u(const void* p) {
  uint32_t a;
  asm("{ .reg .u64 t; cvta.to.shared.u64 t, %1; cvt.u32.u64 %0, t; }" : "=r"(a) : "l"(p));
  return a;
}
#define CPA16(dst, src, sz) \
  asm volatile("cp.async.cg.shared.global [%0], [%1], 16, %2;" \
               :: "r"(dst), "l"(src), "r"(sz) : "memory")
#define CPA_COMMIT() asm volatile("cp.async.commit_group;" ::: "memory")
#define CPA_WAIT0() asm volatile("cp.async.wait_group 0;" ::: "memory")
#define CPA_WAIT1() asm volatile("cp.async.wait_group 1;" ::: "memory")

__device__ __forceinline__ void split2(float a, float b, uint32_t& hi, uint32_t& lo2) {
  __nv_bfloat16 ha = __float2bfloat16_rn(a), hb = __float2bfloat16_rn(b);
  __nv_bfloat16 la = __float2bfloat16_rn(a - __bfloat162float(ha));
  __nv_bfloat16 lb = __float2bfloat16_rn(b - __bfloat162float(hb));
  __nv_bfloat162 h2 = __halves2bfloat162(ha, hb), l2 = __halves2bfloat162(la, lb);
  hi = *reinterpret_cast<uint32_t*>(&h2);
  lo2 = *reinterpret_cast<uint32_t*>(&l2);
}
__device__ __forceinline__ void split4(float4 v, uint2& hi, uint2& lo) {
  split2(v.x, v.y, hi.x, lo.x);
  split2(v.z, v.w, hi.y, lo.y);
}
__device__ __forceinline__ float capexp(float s) {
  float xs = s * KXf, x2 = xs * xs;
  float pl = fmaf(x2, C7f, C5f);
  pl = fmaf(x2, pl, C3f);
  pl = fmaf(x2, pl, 1.0f);
  return __expf((CAPf * xs) * pl);
}
__device__ __forceinline__ float clip1(float e, float c1) {
  return fminf(fmaxf(fmaf(e, c1, -0.01f), 0.f), 1.f);
}

// ---- prep: split K and V into bf16 hi/lo arrays ----
__global__ __launch_bounds__(256)
void prep_split(const float* __restrict__ k, const float* __restrict__ v) {
  size_t i = (size_t)blockIdx.x * 256 + threadIdx.x;   // one float4
  if (i >= KVELEMS / 4) return;
  uint2 hi, lo;
  float4 kv = reinterpret_cast<const float4*>(k)[i];
  split4(kv, hi, lo);
  reinterpret_cast<uint2*>(gKH)[i] = hi;
  reinterpret_cast<uint2*>(gKL)[i] = lo;
  float4 vv = reinterpret_cast<const float4*>(v)[i];
  split4(vv, hi, lo);
  reinterpret_cast<uint2*>(gVH)[i] = hi;
  reinterpret_cast<uint2*>(gVL)[i] = lo;
}

// stage one 128-row K/V tile (hi+lo) into stage buffer s
__device__ __forceinline__ void stage_tile(uint32_t sb, int s, int tid, int jb, int kend,
                                           const __nv_bfloat16* hb, const __nv_bfloat16* lb) {
#pragma unroll
  for (int it = 0; it < 4; ++it) {
    int m = tid + 512 * it;
    int r = m >> 4, c8 = m & 15, j = jb + r;
    uint32_t sz = (j < kend) ? 16u : 0u;
    size_t roff = (size_t)j * (HKVn * Dn) + 8 * c8;
    uint32_t doff = (uint32_t)(r * PQn) * 2 + 16 * c8;
    CPA16(sb + O_KS(s) + doff, hb + roff, sz);
    CPA16(sb + O_KSL(s) + doff, lb + roff, sz);
  }
  CPA_COMMIT();
}

__global__ __launch_bounds__(512, 1)
void swa_mma(const float* __restrict__ q, float* __restrict__ out) {
  extern __shared__ char sm[];
  const uint32_t sb = s2u(sm);
  float* sums = reinterpret_cast<float*>(sm + O_SUMS);

  const int tid = threadIdx.x, w = tid >> 5, lane = tid & 31;
  const int mh = w & 3, nb = w >> 2;          // warp -> (m-quarter, n-quarter)
  const int quad = lane >> 2, c2 = (lane & 3) * 2;
  const int r0 = 16 * mh + quad, r1 = r0 + 8; // same head, qpos and qpos+8
  const int qb = blockIdx.x, kvh = blockIdx.y, b = blockIdx.z;
  const int qs = qb * QPn;
  const int lo = (qs > WINn) ? (qs - WINn) : 0;
  const int kend = qs + QPn;                  // exclusive kv bound
  const int nt = (kend - lo + KTn - 1) >> 7;
  const int cta = (b * HKVn + kvh) * NQBn + qb;
  float* __restrict__ strip = g_strip + (size_t)cta * (QTn * SPn);

  // ---- init sums + load/split Q (64 rows = 4 heads x 16 qpos, 128 d) ----
  if (tid < QTn) sums[tid] = 0.f;
  for (int m = tid; m < QTn * 32; m += 512) {
    int r = m >> 5, d4 = m & 31;
    const float* qp = q + (((size_t)(b * SQn + qs + (r & 15)) * HQn) + kvh * 4 + (r >> 4)) * Dn;
    float4 vv = *reinterpret_cast<const float4*>(qp + 4 * d4);
    uint2 hi, lo2;
    split4(vv, hi, lo2);
    uint32_t off = (uint32_t)(r * PQn + 4 * d4) * 2;
    *reinterpret_cast<uint2*>(sm + O_QH + off) = hi;
    *reinterpret_cast<uint2*>(sm + O_QL + off) = lo2;
  }

  const size_t kvbase = (size_t)b * SQn * HKVn * Dn + (size_t)kvh * Dn;
  const __nv_bfloat16* khb = gKH + kvbase;
  const __nv_bfloat16* klb = gKL + kvbase;
  const __nv_bfloat16* vhb = gVH + kvbase;
  const __nv_bfloat16* vlb = gVL + kvbase;

  // ldmatrix lane offsets
  const int aRow = 16 * mh + (lane & 7) + 8 * ((lane >> 3) & 1);
  const int aColB = 8 * ((lane >> 4) & 1);
  const int kRow = (lane & 7) + 8 * ((lane >> 4) & 1);
  const int kColB = 8 * ((lane >> 3) & 1);
  const int vRow = (lane & 7) + 8 * ((lane >> 3) & 1);
  const int vColB = 8 * ((lane >> 4) & 1);

  const int i0 = qs + quad, i1 = qs + quad + 8;   // q positions of r0 / r1

  // ======================= QK phase (double-buffered) =======================
  float ssum0 = 0.f, ssum1 = 0.f;
  stage_tile(sb, 0, tid, lo, kend, khb, klb);
  for (int t = 0; t < nt; ++t) {
    if (t + 1 < nt) {
      stage_tile(sb, (t + 1) & 1, tid, lo + (t + 1) * KTn, kend, khb, klb);
      CPA_WAIT1();
    } else {
      CPA_WAIT0();
    }
    __syncthreads();
    const int jb = lo + t * KTn;
    const uint32_t kh_b = sb + O_KS(t & 1), kl_b = sb + O_KSL(t & 1);

    float acc[4][4] = {};
#pragma unroll
    for (int ks = 0; ks < 8; ++ks) {
      uint32_t ah[4], al[4], bh[4], bl[4];
      uint32_t aoff = (uint32_t)(aRow * PQn + 16 * ks + aColB) * 2;
      ldsm4(sb + O_QH + aoff, ah);
      ldsm4(sb + O_QL + aoff, al);
#pragma unroll
      for (int p = 0; p < 2; ++p) {
        uint32_t boff = (uint32_t)((32 * nb + 16 * p + kRow) * PQn + 16 * ks + kColB) * 2;
        ldsm4(kh_b + boff, bh);
        ldsm4(kl_b + boff, bl);
        mma16816(acc[2 * p], ah, bh[0], bh[1]);
        mma16816(acc[2 * p], ah, bl[0], bl[1]);
        mma16816(acc[2 * p], al, bh[0], bh[1]);
        mma16816(acc[2 * p + 1], ah, bh[2], bh[3]);
        mma16816(acc[2 * p + 1], ah, bl[2], bl[3]);
        mma16816(acc[2 * p + 1], al, bh[2], bh[3]);
      }
    }
    // epilogue: cap/exp/mask -> permuted strip (float4) + register sums
    float f0[4][2], f1[4][2];
#pragma unroll
    for (int j4 = 0; j4 < 4; ++j4) {
      const int cb = 32 * nb + 8 * j4 + c2;
      const int jg = jb + cb;
      f0[j4][0] = (jg >= i0 - WINn && jg <= i0) ? capexp(acc[j4][0]) : 0.f;
      f0[j4][1] = (jg + 1 >= i0 - WINn && jg + 1 <= i0) ? capexp(acc[j4][1]) : 0.f;
      f1[j4][0] = (jg >= i1 - WINn && jg <= i1) ? capexp(acc[j4][2]) : 0.f;
      f1[j4][1] = (jg + 1 >= i1 - WINn && jg + 1 <= i1) ? capexp(acc[j4][3]) : 0.f;
      ssum0 += f0[j4][0] + f0[j4][1];
      ssum1 += f1[j4][0] + f1[j4][1];
    }
#pragma unroll
    for (int g = 0; g < 2; ++g) {
      const int ph = t * KTn + 32 * nb + 16 * g + 2 * c2;
      float4 w0 = make_float4(f0[2 * g][0], f0[2 * g][1], f0[2 * g + 1][0], f0[2 * g + 1][1]);
      float4 w1 = make_float4(f1[2 * g][0], f1[2 * g][1], f1[2 * g + 1][0], f1[2 * g + 1][1]);
      __stcg(reinterpret_cast<float4*>(&strip[r0 * SPn + ph]), w0);
      __stcg(reinterpret_cast<float4*>(&strip[r1 * SPn + ph]), w1);
    }
    __syncthreads();   // all warps done with buffer (t&1) before restage
  }

  // ---- row sums: 4-lane shfl reduce, one atomic per row ----
  ssum0 += __shfl_xor_sync(0xffffffffu, ssum0, 1);
  ssum0 += __shfl_xor_sync(0xffffffffu, ssum0, 2);
  ssum1 += __shfl_xor_sync(0xffffffffu, ssum1, 1);
  ssum1 += __shfl_xor_sync(0xffffffffu, ssum1, 2);
  if ((lane & 3) == 0) {
    atomicAdd(&sums[r0], ssum0);
    atomicAdd(&sums[r1], ssum1);
  }
  __syncthreads();

  // ======================= PV phase (double-buffered) =======================
  const float c1a = 1.02f / sums[r0], c1b = 1.02f / sums[r1];
  float oacc[4][4] = {};
  stage_tile(sb, 0, tid, lo, kend, vhb, vlb);
  for (int t = 0; t < nt; ++t) {
    if (t + 1 < nt) {
      stage_tile(sb, (t + 1) & 1, tid, lo + (t + 1) * KTn, kend, vhb, vlb);
      CPA_WAIT1();
    } else {
      CPA_WAIT0();
    }
    __syncthreads();
    const uint32_t vh_b = sb + O_KS(t & 1), vl_b = sb + O_KSL(t & 1);

#pragma unroll
    for (int ks = 0; ks < 8; ++ks) {
      const int ph = t * KTn + 16 * ks + 2 * c2;   // permuted: {c2,c2+1,c2+8,c2+9}
      float4 P0 = __ldcg(reinterpret_cast<const float4*>(&strip[r0 * SPn + ph]));
      float4 P1 = __ldcg(reinterpret_cast<const float4*>(&strip[r1 * SPn + ph]));
      float a00 = clip1(P0.x, c1a), a01 = clip1(P0.y, c1a);
      float a02 = clip1(P0.z, c1a), a03 = clip1(P0.w, c1a);
      float a10 = clip1(P1.x, c1b), a11 = clip1(P1.y, c1b);
      float a12 = clip1(P1.z, c1b), a13 = clip1(P1.w, c1b);
      uint32_t ah[4], al[4];
      split2(a00, a01, ah[0], al[0]);
      split2(a10, a11, ah[1], al[1]);
      split2(a02, a03, ah[2], al[2]);
      split2(a12, a13, ah[3], al[3]);
#pragma unroll
      for (int p = 0; p < 2; ++p) {
        uint32_t bh[4], bl[4];
        uint32_t boff = (uint32_t)((16 * ks + vRow) * PQn + 32 * nb + 16 * p + vColB) * 2;
        ldsm4t(vh_b + boff, bh);
        ldsm4t(vl_b + boff, bl);
        mma16816(oacc[2 * p], ah, bh[0], bh[1]);
        mma16816(oacc[2 * p], ah, bl[0], bl[1]);
        mma16816(oacc[2 * p], al, bh[0], bh[1]);
        mma16816(oacc[2 * p + 1], ah, bh[2], bh[3]);
        mma16816(oacc[2 * p + 1], ah, bl[2], bl[3]);
        mma16816(oacc[2 * p + 1], al, bh[2], bh[3]);
      }
    }
    __syncthreads();
  }

  // ---- stage output through smem (reuse stage buffer 0), coalesced store ----
  float* ostage = reinterpret_cast<float*>(sm + O_KS(0));   // 64 x 132 f32
#pragma unroll
  for (int j4 = 0; j4 < 4; ++j4) {
    const int cb = 32 * nb + 8 * j4 + c2;
    *reinterpret_cast<float2*>(&ostage[r0 * 132 + cb]) = make_float2(oacc[j4][0], oacc[j4][1]);
    *reinterpret_cast<float2*>(&ostage[r1 * 132 + cb]) = make_float2(oacc[j4][2], oacc[j4][3]);
  }
  __syncthreads();
  for (int m = tid; m < QTn * 32; m += 512) {
    int r = m >> 5, d4 = m & 31;
    float* op = out + (((size_t)(b * SQn + qs + (r & 15)) * HQn) + kvh * 4 + (r >> 4)) * Dn;
    *reinterpret_cast<float4*>(op + 4 * d4) =
        *reinterpret_cast<const float4*>(&ostage[r * 132 + 4 * d4]);
  }
}

extern "C" void kernel_launch(void* const* d_in, const int* in_sizes, int n_in,
                              void* d_out, int out_size) {
  (void)in_sizes; (void)n_in; (void)out_size;
  const float* q = (const float*)d_in[0];
  const float* k = (const float*)d_in[1];
  const float* v = (const float*)d_in[2];
  float* out = (float*)d_out;
  cudaFuncSetAttribute(swa_mma, cudaFuncAttributeMaxDynamicSharedMemorySize, SMEM_SZ);
  prep_split<<<(int)((KVELEMS / 4 + 255) / 256), 256>>>(k, v);
  dim3 grid(NQBn, HKVn, 2);
  swa_mma<<<grid, 512, SMEM_SZ>>>(q, out);
}

// round 15
// speedup vs baseline: 1.5328x; 1.5328x over previous
#include <cuda_runtime.h>
#include <cuda_bf16.h>
#include <stdint.h>

#define SQn 2048
#define HQn 32
#define HKVn 8
#define Dn 128
#define WINn 512
#define QPn 8                /* q positions per CTA */
#define QTn 32               /* rows per CTA = QPn * 4 heads */
#define KTn 64               /* kv rows per staged tile */
#define NQBn 256             /* q blocks = SQn / QPn */
#define NCTAn 4096
#define SPn 640              /* gmem strip pitch (f32) */
#define PQn 136              /* bf16 tile pitch: 272B rows -> LDSM conflict-free */
#define SCALEf 0.088388347648318447f
#define CAPf 30.0f
#define KXf (SCALEf / CAPf)
#define C3f (-0.33333334f)
#define C5f (0.13333333f)
#define C7f (-0.05396825f)

// ---- smem layout (bytes) ----
#define O_QH 0               /* 32*136*2 = 8704 */
#define O_QL 8704
#define O_KS(s) (17408 + (s) * 34816)   /* stage s: hi (17408B) */
#define O_KSL(s) (O_KS(s) + 17408)      /* stage s: lo */
#define O_SUMS 87040         /* 32 f32 */
#define SMEM_SZ 87168

#define KVELEMS ((size_t)2 * SQn * HKVn * Dn)

__device__ float g_strip[(size_t)NCTAn * QTn * SPn];   // L2-resident scratch
__device__ __nv_bfloat16 gKH[KVELEMS];
__device__ __nv_bfloat16 gKL[KVELEMS];
__device__ __nv_bfloat16 gVH[KVELEMS];
__device__ __nv_bfloat16 gVL[KVELEMS];

__device__ __forceinline__ void ldsm4(uint32_t a, uint32_t r[4]) {
  asm volatile("ldmatrix.sync.aligned.m8n8.x4.shared.b16 {%0,%1,%2,%3}, [%4];"
               : "=r"(r[0]), "=r"(r[1]), "=r"(r[2]), "=r"(r[3]) : "r"(a));
}
__device__ __forceinline__ void ldsm4t(uint32_t a, uint32_t r[4]) {
  asm volatile("ldmatrix.sync.aligned.m8n8.x4.trans.shared.b16 {%0,%1,%2,%3}, [%4];"
               : "=r"(r[0]), "=r"(r[1]), "=r"(r[2]), "=r"(r[3]) : "r"(a));
}
__device__ __forceinline__ void mma16816(float c[4], const uint32_t a[4],
                                         uint32_t b0, uint32_t b1) {
  asm volatile(
      "mma.sync.aligned.m16n8k16.row.col.f32.bf16.bf16.f32 "
      "{%0,%1,%2,%3},{%4,%5,%6,%7},{%8,%9},{%0,%1,%2,%3};"
      : "+f"(c[0]), "+f"(c[1]), "+f"(c[2]), "+f"(c[3])
      : "r"(a[0]), "r"(a[1]), "r"(a[2]), "r"(a[3]), "r"(b0), "r"(b1));
}
__device__ __forceinline__ uint32_t s2u(const void* p) {
  uint32_t a;
  asm("{ .reg .u64 t; cvta.to.shared.u64 t, %1; cvt.u32.u64 %0, t; }" : "=r"(a) : "l"(p));
  return a;
}
#define CPA16(dst, src, sz) \
  asm volatile("cp.async.cg.shared.global [%0], [%1], 16, %2;" \
               :: "r"(dst), "l"(src), "r"(sz) : "memory")
#define CPA_COMMIT() asm volatile("cp.async.commit_group;" ::: "memory")
#define CPA_WAIT0() asm volatile("cp.async.wait_group 0;" ::: "memory")
#define CPA_WAIT1() asm volatile("cp.async.wait_group 1;" ::: "memory")

__device__ __forceinline__ void split2(float a, float b, uint32_t& hi, uint32_t& lo2) {
  __nv_bfloat16 ha = __float2bfloat16_rn(a), hb = __float2bfloat16_rn(b);
  __nv_bfloat16 la = __float2bfloat16_rn(a - __bfloat162float(ha));
  __nv_bfloat16 lb = __float2bfloat16_rn(b - __bfloat162float(hb));
  __nv_bfloat162 h2 = __halves2bfloat162(ha, hb), l2 = __halves2bfloat162(la, lb);
  hi = *reinterpret_cast<uint32_t*>(&h2);
  lo2 = *reinterpret_cast<uint32_t*>(&l2);
}
__device__ __forceinline__ void split4(float4 v, uint2& hi, uint2& lo) {
  split2(v.x, v.y, hi.x, lo.x);
  split2(v.z, v.w, hi.y, lo.y);
}
__device__ __forceinline__ float capexp(float s) {
  float xs = s * KXf, x2 = xs * xs;
  float pl = fmaf(x2, C7f, C5f);
  pl = fmaf(x2, pl, C3f);
  pl = fmaf(x2, pl, 1.0f);
  return __expf((CAPf * xs) * pl);
}
__device__ __forceinline__ float clip1(float e, float c1) {
  return fminf(fmaxf(fmaf(e, c1, -0.01f), 0.f), 1.f);
}

// ---- prep: split K and V into bf16 hi/lo arrays ----
__global__ __launch_bounds__(256)
void prep_split(const float* __restrict__ k, const float* __restrict__ v) {
  size_t i = (size_t)blockIdx.x * 256 + threadIdx.x;   // one float4
  if (i >= KVELEMS / 4) return;
  uint2 hi, lo;
  float4 kv = reinterpret_cast<const float4*>(k)[i];
  split4(kv, hi, lo);
  reinterpret_cast<uint2*>(gKH)[i] = hi;
  reinterpret_cast<uint2*>(gKL)[i] = lo;
  float4 vv = reinterpret_cast<const float4*>(v)[i];
  split4(vv, hi, lo);
  reinterpret_cast<uint2*>(gVH)[i] = hi;
  reinterpret_cast<uint2*>(gVL)[i] = lo;
}

// stage one 64-row K/V tile (hi+lo) into stage buffer s (256 threads)
__device__ __forceinline__ void stage_tile(uint32_t sb, int s, int tid, int jb, int kend,
                                           const __nv_bfloat16* hb, const __nv_bfloat16* lb) {
#pragma unroll
  for (int it = 0; it < 4; ++it) {
    int m = tid + 256 * it;                  // 1024 chunks = 64 rows x 16
    int r = m >> 4, c8 = m & 15, j = jb + r;
    uint32_t sz = (j < kend) ? 16u : 0u;
    size_t roff = (size_t)j * (HKVn * Dn) + 8 * c8;
    uint32_t doff = (uint32_t)(r * PQn) * 2 + 16 * c8;
    CPA16(sb + O_KS(s) + doff, hb + roff, sz);
    CPA16(sb + O_KSL(s) + doff, lb + roff, sz);
  }
  CPA_COMMIT();
}

__global__ __launch_bounds__(256, 2)
void swa_mma(const float* __restrict__ q, float* __restrict__ out) {
  extern __shared__ char sm[];
  const uint32_t sb = s2u(sm);
  float* sums = reinterpret_cast<float*>(sm + O_SUMS);

  const int tid = threadIdx.x, w = tid >> 5, lane = tid & 31;
  const int mh = w & 1, nb = w >> 1;          // warp -> (m-half, n-quarter)
  const int quad = lane >> 2, c2 = (lane & 3) * 2;
  const int r0 = 16 * mh + quad, r1 = r0 + 8; // rows: same q-pos, adjacent heads
  const int qb = blockIdx.x, kvh = blockIdx.y, b = blockIdx.z;
  const int qs8 = qb * QPn;
  const int lo = (qs8 > WINn) ? (qs8 - WINn) : 0;
  const int kend = qs8 + QPn;                 // exclusive kv bound
  const int nt = (kend - lo + KTn - 1) >> 6;  // 64-row tiles
  const int cta = (b * HKVn + kvh) * NQBn + qb;
  float* __restrict__ strip = g_strip + (size_t)cta * (QTn * SPn);

  // ---- init sums + load/split Q (32 rows = 4 heads x 8 qpos, 128 d) ----
  if (tid < QTn) sums[tid] = 0.f;
  for (int m = tid; m < QTn * 32; m += 256) {
    int r = m >> 5, d4 = m & 31;
    const float* qp = q + (((size_t)(b * SQn + qs8 + (r & 7)) * HQn) + kvh * 4 + (r >> 3)) * Dn;
    float4 vv = *reinterpret_cast<const float4*>(qp + 4 * d4);
    uint2 hi, lo2;
    split4(vv, hi, lo2);
    uint32_t off = (uint32_t)(r * PQn + 4 * d4) * 2;
    *reinterpret_cast<uint2*>(sm + O_QH + off) = hi;
    *reinterpret_cast<uint2*>(sm + O_QL + off) = lo2;
  }

  const size_t kvbase = (size_t)b * SQn * HKVn * Dn + (size_t)kvh * Dn;
  const __nv_bfloat16* khb = gKH + kvbase;
  const __nv_bfloat16* klb = gKL + kvbase;
  const __nv_bfloat16* vhb = gVH + kvbase;
  const __nv_bfloat16* vlb = gVL + kvbase;

  // ldmatrix lane offsets
  const int aRow = 16 * mh + (lane & 7) + 8 * ((lane >> 3) & 1);
  const int aColB = 8 * ((lane >> 4) & 1);
  const int kRow = (lane & 7) + 8 * ((lane >> 4) & 1);
  const int kColB = 8 * ((lane >> 3) & 1);
  const int vRow = (lane & 7) + 8 * ((lane >> 3) & 1);
  const int vColB = 8 * ((lane >> 4) & 1);

  // ======================= QK phase (double-buffered 64-row tiles) =======================
  float ssum0 = 0.f, ssum1 = 0.f;
  const int i0 = qs8 + quad;                  // q position for BOTH r0 and r1
  stage_tile(sb, 0, tid, lo, kend, khb, klb);
  for (int t = 0; t < nt; ++t) {
    if (t + 1 < nt) {
      stage_tile(sb, (t + 1) & 1, tid, lo + (t + 1) * KTn, kend, khb, klb);
      CPA_WAIT1();
    } else {
      CPA_WAIT0();
    }
    __syncthreads();
    const int jb = lo + t * KTn;
    const uint32_t kh_b = sb + O_KS(t & 1), kl_b = sb + O_KSL(t & 1);

    float acc[2][4] = {};
#pragma unroll
    for (int ks = 0; ks < 8; ++ks) {
      uint32_t ah[4], al[4], bh[4], bl[4];
      uint32_t aoff = (uint32_t)(aRow * PQn + 16 * ks + aColB) * 2;
      ldsm4(sb + O_QH + aoff, ah);
      ldsm4(sb + O_QL + aoff, al);
      uint32_t boff = (uint32_t)((16 * nb + kRow) * PQn + 16 * ks + kColB) * 2;
      ldsm4(kh_b + boff, bh);
      ldsm4(kl_b + boff, bl);
      mma16816(acc[0], ah, bh[0], bh[1]);
      mma16816(acc[0], ah, bl[0], bl[1]);
      mma16816(acc[0], al, bh[0], bh[1]);
      mma16816(acc[1], ah, bh[2], bh[3]);
      mma16816(acc[1], ah, bl[2], bl[3]);
      mma16816(acc[1], al, bh[2], bh[3]);
    }
    // epilogue: cap/exp/mask -> permuted strip (float4) + register sums
    float f0[2][2], f1[2][2];
#pragma unroll
    for (int j4 = 0; j4 < 2; ++j4) {
      const int cb = 16 * nb + 8 * j4 + c2;
      const int jg = jb + cb;
      const bool ok0 = (jg >= i0 - WINn) && (jg <= i0);
      const bool ok1 = (jg + 1 >= i0 - WINn) && (jg + 1 <= i0);
      f0[j4][0] = ok0 ? capexp(acc[j4][0]) : 0.f;
      f0[j4][1] = ok1 ? capexp(acc[j4][1]) : 0.f;
      f1[j4][0] = ok0 ? capexp(acc[j4][2]) : 0.f;
      f1[j4][1] = ok1 ? capexp(acc[j4][3]) : 0.f;
      ssum0 += f0[j4][0] + f0[j4][1];
      ssum1 += f1[j4][0] + f1[j4][1];
    }
    {
      const int ph = t * KTn + 16 * nb + 2 * c2;  // group index = t*4 + nb
      float4 w0 = make_float4(f0[0][0], f0[0][1], f0[1][0], f0[1][1]);
      float4 w1 = make_float4(f1[0][0], f1[0][1], f1[1][0], f1[1][1]);
      __stcg(reinterpret_cast<float4*>(&strip[r0 * SPn + ph]), w0);
      __stcg(reinterpret_cast<float4*>(&strip[r1 * SPn + ph]), w1);
    }
    __syncthreads();   // all warps done with buffer (t&1) before restage
  }

  // ---- row sums: 4-lane shfl reduce, one atomic per row ----
  ssum0 += __shfl_xor_sync(0xffffffffu, ssum0, 1);
  ssum0 += __shfl_xor_sync(0xffffffffu, ssum0, 2);
  ssum1 += __shfl_xor_sync(0xffffffffu, ssum1, 1);
  ssum1 += __shfl_xor_sync(0xffffffffu, ssum1, 2);
  if ((lane & 3) == 0) {
    atomicAdd(&sums[r0], ssum0);
    atomicAdd(&sums[r1], ssum1);
  }
  __syncthreads();

  // ======================= PV phase (double-buffered 64-row tiles) =======================
  const float c1a = 1.02f / sums[r0], c1b = 1.02f / sums[r1];
  float oacc[4][4] = {};
  stage_tile(sb, 0, tid, lo, kend, vhb, vlb);
  for (int t = 0; t < nt; ++t) {
    if (t + 1 < nt) {
      stage_tile(sb, (t + 1) & 1, tid, lo + (t + 1) * KTn, kend, vhb, vlb);
      CPA_WAIT1();
    } else {
      CPA_WAIT0();
    }
    __syncthreads();
    const uint32_t vh_b = sb + O_KS(t & 1), vl_b = sb + O_KSL(t & 1);

#pragma unroll
    for (int ks = 0; ks < 4; ++ks) {          // 4 x 16 kv rows per 64-tile
      const int ph = t * KTn + 16 * ks + 2 * c2;   // permuted: {c2,c2+1,c2+8,c2+9}
      float4 P0 = __ldcg(reinterpret_cast<const float4*>(&strip[r0 * SPn + ph]));
      float4 P1 = __ldcg(reinterpret_cast<const float4*>(&strip[r1 * SPn + ph]));
      float a00 = clip1(P0.x, c1a), a01 = clip1(P0.y, c1a);
      float a02 = clip1(P0.z, c1a), a03 = clip1(P0.w, c1a);
      float a10 = clip1(P1.x, c1b), a11 = clip1(P1.y, c1b);
      float a12 = clip1(P1.z, c1b), a13 = clip1(P1.w, c1b);
      uint32_t ah[4], al[4];
      split2(a00, a01, ah[0], al[0]);
      split2(a10, a11, ah[1], al[1]);
      split2(a02, a03, ah[2], al[2]);
      split2(a12, a13, ah[3], al[3]);
#pragma unroll
      for (int p = 0; p < 2; ++p) {
        uint32_t bh[4], bl[4];
        uint32_t boff = (uint32_t)((16 * ks + vRow) * PQn + 32 * nb + 16 * p + vColB) * 2;
        ldsm4t(vh_b + boff, bh);
        ldsm4t(vl_b + boff, bl);
        mma16816(oacc[2 * p], ah, bh[0], bh[1]);
        mma16816(oacc[2 * p], ah, bl[0], bl[1]);
        mma16816(oacc[2 * p], al, bh[0], bh[1]);
        mma16816(oacc[2 * p + 1], ah, bh[2], bh[3]);
        mma16816(oacc[2 * p + 1], ah, bl[2], bl[3]);
        mma16816(oacc[2 * p + 1], al, bh[2], bh[3]);
      }
    }
    __syncthreads();
  }

  // ---- stage output through smem (reuse stage buffer 0), coalesced store ----
  float* ostage = reinterpret_cast<float*>(sm + O_KS(0));   // 32 x 132 f32
#pragma unroll
  for (int j4 = 0; j4 < 4; ++j4) {
    const int cb = 32 * nb + 8 * j4 + c2;
    *reinterpret_cast<float2*>(&ostage[r0 * 132 + cb]) = make_float2(oacc[j4][0], oacc[j4][1]);
    *reinterpret_cast<float2*>(&ostage[r1 * 132 + cb]) = make_float2(oacc[j4][2], oacc[j4][3]);
  }
  __syncthreads();
  for (int m = tid; m < QTn * 32; m += 256) {
    int r = m >> 5, d4 = m & 31;
    float* op = out + (((size_t)(b * SQn + qs8 + (r & 7)) * HQn) + kvh * 4 + (r >> 3)) * Dn;
    *reinterpret_cast<float4*>(op + 4 * d4) =
        *reinterpret_cast<const float4*>(&ostage[r * 132 + 4 * d4]);
  }
}

extern "C" void kernel_launch(void* const* d_in, const int* in_sizes, int n_in,
                              void* d_out, int out_size) {
  (void)in_sizes; (void)n_in; (void)out_size;
  const float* q = (const float*)d_in[0];
  const float* k = (const float*)d_in[1];
  const float* v = (const float*)d_in[2];
  float* out = (float*)d_out;
  cudaFuncSetAttribute(swa_mma, cudaFuncAttributeMaxDynamicSharedMemorySize, SMEM_SZ);
  prep_split<<<(int)((KVELEMS / 4 + 255) / 256), 256>>>(k, v);
  dim3 grid(NQBn, HKVn, 2);
  swa_mma<<<grid, 256, SMEM_SZ>>>(q, out);
}

// round 16
// speedup vs baseline: 1.7229x; 1.1240x over previous
#include <cuda_runtime.h>
#include <cuda_bf16.h>
#include <stdint.h>

#define SQn 2048
#define HQn 32
#define HKVn 8
#define Dn 128
#define WINn 512
#define QPn 8                /* q positions per CTA */
#define QTn 32               /* rows per CTA = QPn * 4 heads */
#define KTn 64               /* kv rows per staged tile */
#define NQBn 256             /* q blocks = SQn / QPn */
#define NCTAn 4096
#define SPn 640              /* gmem strip pitch (f32) */
#define PQn 136              /* bf16 tile pitch: 272B rows -> LDSM conflict-free */
#define SCALEf 0.088388347648318447f
#define CAPf 30.0f
#define KXf (SCALEf / CAPf)
#define C3f (-0.33333334f)
#define C5f (0.13333333f)
#define C7f (-0.05396825f)

// ---- smem layout (bytes) ----
#define O_QH 0               /* 32*136*2 = 8704 */
#define O_QL 8704
#define O_KS(s) (17408 + (s) * 34816)   /* stage s: hi (17408B) */
#define O_KSL(s) (O_KS(s) + 17408)      /* stage s: lo */
#define O_SUMS 87040         /* 32 f32 */
#define SMEM_SZ 87168

#define KVELEMS ((size_t)2 * SQn * HKVn * Dn)

__device__ float g_strip[(size_t)NCTAn * QTn * SPn];   // L2-resident scratch
__device__ __nv_bfloat16 gKH[KVELEMS];
__device__ __nv_bfloat16 gKL[KVELEMS];
__device__ __nv_bfloat16 gVH[KVELEMS];
__device__ __nv_bfloat16 gVL[KVELEMS];

__device__ __forceinline__ void ldsm4(uint32_t a, uint32_t r[4]) {
  asm volatile("ldmatrix.sync.aligned.m8n8.x4.shared.b16 {%0,%1,%2,%3}, [%4];"
               : "=r"(r[0]), "=r"(r[1]), "=r"(r[2]), "=r"(r[3]) : "r"(a));
}
__device__ __forceinline__ void ldsm4t(uint32_t a, uint32_t r[4]) {
  asm volatile("ldmatrix.sync.aligned.m8n8.x4.trans.shared.b16 {%0,%1,%2,%3}, [%4];"
               : "=r"(r[0]), "=r"(r[1]), "=r"(r[2]), "=r"(r[3]) : "r"(a));
}
__device__ __forceinline__ void mma16816(float c[4], const uint32_t a[4],
                                         uint32_t b0, uint32_t b1) {
  asm volatile(
      "mma.sync.aligned.m16n8k16.row.col.f32.bf16.bf16.f32 "
      "{%0,%1,%2,%3},{%4,%5,%6,%7},{%8,%9},{%0,%1,%2,%3};"
      : "+f"(c[0]), "+f"(c[1]), "+f"(c[2]), "+f"(c[3])
      : "r"(a[0]), "r"(a[1]), "r"(a[2]), "r"(a[3]), "r"(b0), "r"(b1));
}
__device__ __forceinline__ uint32_t s2u(const void* p) {
  uint32_t a;
  asm("{ .reg .u64 t; cvta.to.shared.u64 t, %1; cvt.u32.u64 %0, t; }" : "=r"(a) : "l"(p));
  return a;
}
#define CPA16(dst, src, sz) \
  asm volatile("cp.async.cg.shared.global [%0], [%1], 16, %2;" \
               :: "r"(dst), "l"(src), "r"(sz) : "memory")
#define CPA_COMMIT() asm volatile("cp.async.commit_group;" ::: "memory")
#define CPA_WAIT0() asm volatile("cp.async.wait_group 0;" ::: "memory")

__device__ __forceinline__ void split2(float a, float b, uint32_t& hi, uint32_t& lo2) {
  __nv_bfloat16 ha = __float2bfloat16_rn(a), hb = __float2bfloat16_rn(b);
  __nv_bfloat16 la = __float2bfloat16_rn(a - __bfloat162float(ha));
  __nv_bfloat16 lb = __float2bfloat16_rn(b - __bfloat162float(hb));
  __nv_bfloat162 h2 = __halves2bfloat162(ha, hb), l2 = __halves2bfloat162(la, lb);
  hi = *reinterpret_cast<uint32_t*>(&h2);
  lo2 = *reinterpret_cast<uint32_t*>(&l2);
}
__device__ __forceinline__ void split4(float4 v, uint2& hi, uint2& lo) {
  split2(v.x, v.y, hi.x, lo.x);
  split2(v.z, v.w, hi.y, lo.y);
}
__device__ __forceinline__ float capexp(float s) {
  float xs = s * KXf, x2 = xs * xs;
  float pl = fmaf(x2, C7f, C5f);
  pl = fmaf(x2, pl, C3f);
  pl = fmaf(x2, pl, 1.0f);
  return __expf((CAPf * xs) * pl);
}
__device__ __forceinline__ float clip1(float e, float c1) {
  return fminf(fmaxf(fmaf(e, c1, -0.01f), 0.f), 1.f);
}

// ---- prep: split K and V into bf16 hi/lo arrays ----
__global__ __launch_bounds__(256)
void prep_split(const float* __restrict__ k, const float* __restrict__ v) {
  size_t i = (size_t)blockIdx.x * 256 + threadIdx.x;   // one float4
  if (i >= KVELEMS / 4) return;
  uint2 hi, lo;
  float4 kv = reinterpret_cast<const float4*>(k)[i];
  split4(kv, hi, lo);
  reinterpret_cast<uint2*>(gKH)[i] = hi;
  reinterpret_cast<uint2*>(gKL)[i] = lo;
  float4 vv = reinterpret_cast<const float4*>(v)[i];
  split4(vv, hi, lo);
  reinterpret_cast<uint2*>(gVH)[i] = hi;
  reinterpret_cast<uint2*>(gVL)[i] = lo;
}

// stage one 64-row K/V tile (hi+lo) into stage buffer s (256 threads)
__device__ __forceinline__ void stage_tile(uint32_t sb, int s, int tid, int jb, int kend,
                                           const __nv_bfloat16* hb, const __nv_bfloat16* lb) {
#pragma unroll
  for (int it = 0; it < 4; ++it) {
    int m = tid + 256 * it;                  // 1024 chunks = 64 rows x 16
    int r = m >> 4, c8 = m & 15, j = jb + r;
    uint32_t sz = (j < kend) ? 16u : 0u;
    size_t roff = (size_t)j * (HKVn * Dn) + 8 * c8;
    uint32_t doff = (uint32_t)(r * PQn) * 2 + 16 * c8;
    CPA16(sb + O_KS(s) + doff, hb + roff, sz);
    CPA16(sb + O_KSL(s) + doff, lb + roff, sz);
  }
  CPA_COMMIT();
}

__global__ __launch_bounds__(256, 2)
void swa_mma(const float* __restrict__ q, float* __restrict__ out) {
  extern __shared__ char sm[];
  const uint32_t sb = s2u(sm);
  float* sums = reinterpret_cast<float*>(sm + O_SUMS);

  const int tid = threadIdx.x, w = tid >> 5, lane = tid & 31;
  const int mh = w & 1, nb = w >> 1;          // warp -> (m-half, n-quarter)
  const int quad = lane >> 2, c2 = (lane & 3) * 2;
  const int r0 = 16 * mh + quad, r1 = r0 + 8; // rows: same q-pos, adjacent heads
  const int qb = blockIdx.x, kvh = blockIdx.y, b = blockIdx.z;
  const int qs8 = qb * QPn;
  const int lo = (qs8 > WINn) ? (qs8 - WINn) : 0;
  const int kend = qs8 + QPn;                 // exclusive kv bound
  const int nt = (kend - lo + KTn - 1) >> 6;  // 64-row tiles
  const int cta = (b * HKVn + kvh) * NQBn + qb;
  float* __restrict__ strip = g_strip + (size_t)cta * (QTn * SPn);

  // ---- init sums + load/split Q (32 rows = 4 heads x 8 qpos, 128 d) ----
  if (tid < QTn) sums[tid] = 0.f;
  for (int m = tid; m < QTn * 32; m += 256) {
    int r = m >> 5, d4 = m & 31;
    const float* qp = q + (((size_t)(b * SQn + qs8 + (r & 7)) * HQn) + kvh * 4 + (r >> 3)) * Dn;
    float4 vv = *reinterpret_cast<const float4*>(qp + 4 * d4);
    uint2 hi, lo2;
    split4(vv, hi, lo2);
    uint32_t off = (uint32_t)(r * PQn + 4 * d4) * 2;
    *reinterpret_cast<uint2*>(sm + O_QH + off) = hi;
    *reinterpret_cast<uint2*>(sm + O_QL + off) = lo2;
  }

  const size_t kvbase = (size_t)b * SQn * HKVn * Dn + (size_t)kvh * Dn;
  const __nv_bfloat16* khb = gKH + kvbase;
  const __nv_bfloat16* klb = gKL + kvbase;
  const __nv_bfloat16* vhb = gVH + kvbase;
  const __nv_bfloat16* vlb = gVL + kvbase;

  // ldmatrix lane offsets
  const int aRow = 16 * mh + (lane & 7) + 8 * ((lane >> 3) & 1);
  const int aColB = 8 * ((lane >> 4) & 1);
  const int kRow = (lane & 7) + 8 * ((lane >> 4) & 1);
  const int kColB = 8 * ((lane >> 3) & 1);
  const int vRow = (lane & 7) + 8 * ((lane >> 3) & 1);
  const int vColB = 8 * ((lane >> 4) & 1);

  // ======================= QK phase (double-buffered, 1 sync/tile) =======================
  float ssum0 = 0.f, ssum1 = 0.f;
  const int i0 = qs8 + quad;                  // q position for BOTH r0 and r1
  stage_tile(sb, 0, tid, lo, kend, khb, klb);
  for (int t = 0; t < nt; ++t) {
    CPA_WAIT0();
    __syncthreads();            // buffer t ready; all warps done with tile t-1
    if (t + 1 < nt) stage_tile(sb, (t + 1) & 1, tid, lo + (t + 1) * KTn, kend, khb, klb);
    const int jb = lo + t * KTn;
    const uint32_t kh_b = sb + O_KS(t & 1), kl_b = sb + O_KSL(t & 1);

    float acc[2][4] = {};
#pragma unroll
    for (int ks = 0; ks < 8; ++ks) {
      uint32_t ah[4], al[4], bh[4], bl[4];
      uint32_t aoff = (uint32_t)(aRow * PQn + 16 * ks + aColB) * 2;
      ldsm4(sb + O_QH + aoff, ah);
      ldsm4(sb + O_QL + aoff, al);
      uint32_t boff = (uint32_t)((16 * nb + kRow) * PQn + 16 * ks + kColB) * 2;
      ldsm4(kh_b + boff, bh);
      ldsm4(kl_b + boff, bl);
      mma16816(acc[0], ah, bh[0], bh[1]);
      mma16816(acc[0], ah, bl[0], bl[1]);
      mma16816(acc[0], al, bh[0], bh[1]);
      mma16816(acc[1], ah, bh[2], bh[3]);
      mma16816(acc[1], ah, bl[2], bl[3]);
      mma16816(acc[1], al, bh[2], bh[3]);
    }
    // epilogue: cap/exp/mask -> permuted strip (float4) + register sums
    float f0[2][2], f1[2][2];
#pragma unroll
    for (int j4 = 0; j4 < 2; ++j4) {
      const int cb = 16 * nb + 8 * j4 + c2;
      const int jg = jb + cb;
      const bool ok0 = (jg >= i0 - WINn) && (jg <= i0);
      const bool ok1 = (jg + 1 >= i0 - WINn) && (jg + 1 <= i0);
      f0[j4][0] = ok0 ? capexp(acc[j4][0]) : 0.f;
      f0[j4][1] = ok1 ? capexp(acc[j4][1]) : 0.f;
      f1[j4][0] = ok0 ? capexp(acc[j4][2]) : 0.f;
      f1[j4][1] = ok1 ? capexp(acc[j4][3]) : 0.f;
      ssum0 += f0[j4][0] + f0[j4][1];
      ssum1 += f1[j4][0] + f1[j4][1];
    }
    {
      const int ph = t * KTn + 16 * nb + 2 * c2;  // group index = t*4 + nb
      float4 w0 = make_float4(f0[0][0], f0[0][1], f0[1][0], f0[1][1]);
      float4 w1 = make_float4(f1[0][0], f1[0][1], f1[1][0], f1[1][1]);
      __stcg(reinterpret_cast<float4*>(&strip[r0 * SPn + ph]), w0);
      __stcg(reinterpret_cast<float4*>(&strip[r1 * SPn + ph]), w1);
    }
  }

  // ---- row sums: 4-lane shfl reduce, one atomic per row ----
  ssum0 += __shfl_xor_sync(0xffffffffu, ssum0, 1);
  ssum0 += __shfl_xor_sync(0xffffffffu, ssum0, 2);
  ssum1 += __shfl_xor_sync(0xffffffffu, ssum1, 1);
  ssum1 += __shfl_xor_sync(0xffffffffu, ssum1, 2);
  if ((lane & 3) == 0) {
    atomicAdd(&sums[r0], ssum0);
    atomicAdd(&sums[r1], ssum1);
  }
  __syncthreads();              // sums ready; all QK tile reads done

  // ======================= PV phase (double-buffered, 1 sync/tile) =======================
  const float c1a = 1.02f / sums[r0], c1b = 1.02f / sums[r1];
  float oacc[4][4] = {};
  stage_tile(sb, 0, tid, lo, kend, vhb, vlb);
  for (int t = 0; t < nt; ++t) {
    // prefetch this tile's P values (8x float4, L2) BEFORE the staging wait
    float4 P0v[4], P1v[4];
#pragma unroll
    for (int ks = 0; ks < 4; ++ks) {
      const int ph = t * KTn + 16 * ks + 2 * c2;
      P0v[ks] = __ldcg(reinterpret_cast<const float4*>(&strip[r0 * SPn + ph]));
      P1v[ks] = __ldcg(reinterpret_cast<const float4*>(&strip[r1 * SPn + ph]));
    }
    CPA_WAIT0();
    __syncthreads();            // buffer t ready; all warps done with tile t-1
    if (t + 1 < nt) stage_tile(sb, (t + 1) & 1, tid, lo + (t + 1) * KTn, kend, vhb, vlb);
    const uint32_t vh_b = sb + O_KS(t & 1), vl_b = sb + O_KSL(t & 1);

#pragma unroll
    for (int ks = 0; ks < 4; ++ks) {          // 4 x 16 kv rows per 64-tile
      float a00 = clip1(P0v[ks].x, c1a), a01 = clip1(P0v[ks].y, c1a);
      float a02 = clip1(P0v[ks].z, c1a), a03 = clip1(P0v[ks].w, c1a);
      float a10 = clip1(P1v[ks].x, c1b), a11 = clip1(P1v[ks].y, c1b);
      float a12 = clip1(P1v[ks].z, c1b), a13 = clip1(P1v[ks].w, c1b);
      uint32_t ah[4], al[4];
      split2(a00, a01, ah[0], al[0]);
      split2(a10, a11, ah[1], al[1]);
      split2(a02, a03, ah[2], al[2]);
      split2(a12, a13, ah[3], al[3]);
#pragma unroll
      for (int p = 0; p < 2; ++p) {
        uint32_t bh[4], bl[4];
        uint32_t boff = (uint32_t)((16 * ks + vRow) * PQn + 32 * nb + 16 * p + vColB) * 2;
        ldsm4t(vh_b + boff, bh);
        ldsm4t(vl_b + boff, bl);
        mma16816(oacc[2 * p], ah, bh[0], bh[1]);
        mma16816(oacc[2 * p], ah, bl[0], bl[1]);
        mma16816(oacc[2 * p], al, bh[0], bh[1]);
        mma16816(oacc[2 * p + 1], ah, bh[2], bh[3]);
        mma16816(oacc[2 * p + 1], ah, bl[2], bl[3]);
        mma16816(oacc[2 * p + 1], al, bh[2], bh[3]);
      }
    }
  }

  // ---- stage output through smem (reuse stage buffer 0), coalesced store ----
  __syncthreads();              // all PV tile reads done before overwriting buffers
  float* ostage = reinterpret_cast<float*>(sm + O_KS(0));   // 32 x 132 f32
#pragma unroll
  for (int j4 = 0; j4 < 4; ++j4) {
    const int cb = 32 * nb + 8 * j4 + c2;
    *reinterpret_cast<float2*>(&ostage[r0 * 132 + cb]) = make_float2(oacc[j4][0], oacc[j4][1]);
    *reinterpret_cast<float2*>(&ostage[r1 * 132 + cb]) = make_float2(oacc[j4][2], oacc[j4][3]);
  }
  __syncthreads();
  for (int m = tid; m < QTn * 32; m += 256) {
    int r = m >> 5, d4 = m & 31;
    float* op = out + (((size_t)(b * SQn + qs8 + (r & 7)) * HQn) + kvh * 4 + (r >> 3)) * Dn;
    *reinterpret_cast<float4*>(op + 4 * d4) =
        *reinterpret_cast<const float4*>(&ostage[r * 132 + 4 * d4]);
  }
}

extern "C" void kernel_launch(void* const* d_in, const int* in_sizes, int n_in,
                              void* d_out, int out_size) {
  (void)in_sizes; (void)n_in; (void)out_size;
  const float* q = (const float*)d_in[0];
  const float* k = (const float*)d_in[1];
  const float* v = (const float*)d_in[2];
  float* out = (float*)d_out;
  cudaFuncSetAttribute(swa_mma, cudaFuncAttributeMaxDynamicSharedMemorySize, SMEM_SZ);
  prep_split<<<(int)((KVELEMS / 4 + 255) / 256), 256>>>(k, v);
  dim3 grid(NQBn, HKVn, 2);
  swa_mma<<<grid, 256, SMEM_SZ>>>(q, out);
}

// round 17
// speedup vs baseline: 1.9382x; 1.1250x over previous
#include <cuda_runtime.h>
#include <cuda_bf16.h>
#include <stdint.h>

#define SQn 2048
#define HQn 32
#define HKVn 8
#define Dn 128
#define WINn 512
#define QPn 8                /* q positions per CTA */
#define QTn 32               /* rows per CTA = QPn * 4 heads */
#define KTn 64               /* kv rows per staged tile */
#define NQBn 256             /* q blocks = SQn / QPn */
#define NCTAn 4096
#define SPn 640              /* gmem strip pitch (f32) */
#define PQn 136              /* bf16 tile pitch: 272B rows -> LDSM conflict-free */
#define SCALEf 0.088388347648318447f
#define CAPf 30.0f
#define KXf (SCALEf / CAPf)
#define C3f (-0.33333334f)
#define C5f (0.13333333f)
#define C7f (-0.05396825f)

// ---- smem layout (bytes) ----
#define O_QH 0               /* 32*136*2 = 8704 */
#define O_QL 8704
#define O_KH 17408           /* stage hi: 64*136*2 = 17408 */
#define O_KL 34816           /* stage lo */
#define O_SUMS 52224         /* 32 f32 */
#define SMEM_SZ 52480        /* x4 CTAs = 210KB <= 227KB */

#define KVELEMS ((size_t)2 * SQn * HKVn * Dn)

__device__ float g_strip[(size_t)NCTAn * QTn * SPn];   // L2-resident scratch
__device__ __nv_bfloat16 gKH[KVELEMS];
__device__ __nv_bfloat16 gKL[KVELEMS];
__device__ __nv_bfloat16 gVH[KVELEMS];
__device__ __nv_bfloat16 gVL[KVELEMS];

__device__ __forceinline__ void ldsm4(uint32_t a, uint32_t r[4]) {
  asm volatile("ldmatrix.sync.aligned.m8n8.x4.shared.b16 {%0,%1,%2,%3}, [%4];"
               : "=r"(r[0]), "=r"(r[1]), "=r"(r[2]), "=r"(r[3]) : "r"(a));
}
__device__ __forceinline__ void ldsm4t(uint32_t a, uint32_t r[4]) {
  asm volatile("ldmatrix.sync.aligned.m8n8.x4.trans.shared.b16 {%0,%1,%2,%3}, [%4];"
               : "=r"(r[0]), "=r"(r[1]), "=r"(r[2]), "=r"(r[3]) : "r"(a));
}
__device__ __forceinline__ void mma16816(float c[4], const uint32_t a[4],
                                         uint32_t b0, uint32_t b1) {
  asm volatile(
      "mma.sync.aligned.m16n8k16.row.col.f32.bf16.bf16.f32 "
      "{%0,%1,%2,%3},{%4,%5,%6,%7},{%8,%9},{%0,%1,%2,%3};"
      : "+f"(c[0]), "+f"(c[1]), "+f"(c[2]), "+f"(c[3])
      : "r"(a[0]), "r"(a[1]), "r"(a[2]), "r"(a[3]), "r"(b0), "r"(b1));
}
__device__ __forceinline__ uint32_t s2u(const void* p) {
  uint32_t a;
  asm("{ .reg .u64 t; cvta.to.shared.u64 t, %1; cvt.u32.u64 %0, t; }" : "=r"(a) : "l"(p));
  return a;
}
#define CPA16(dst, src, sz) \
  asm volatile("cp.async.cg.shared.global [%0], [%1], 16, %2;" \
               :: "r"(dst), "l"(src), "r"(sz) : "memory")
#define CPA_COMMIT() asm volatile("cp.async.commit_group;" ::: "memory")
#define CPA_WAIT0() asm volatile("cp.async.wait_group 0;" ::: "memory")

__device__ __forceinline__ void split2(float a, float b, uint32_t& hi, uint32_t& lo2) {
  __nv_bfloat16 ha = __float2bfloat16_rn(a), hb = __float2bfloat16_rn(b);
  __nv_bfloat16 la = __float2bfloat16_rn(a - __bfloat162float(ha));
  __nv_bfloat16 lb = __float2bfloat16_rn(b - __bfloat162float(hb));
  __nv_bfloat162 h2 = __halves2bfloat162(ha, hb), l2 = __halves2bfloat162(la, lb);
  hi = *reinterpret_cast<uint32_t*>(&h2);
  lo2 = *reinterpret_cast<uint32_t*>(&l2);
}
__device__ __forceinline__ void split4(float4 v, uint2& hi, uint2& lo) {
  split2(v.x, v.y, hi.x, lo.x);
  split2(v.z, v.w, hi.y, lo.y);
}
__device__ __forceinline__ float capexp(float s) {
  float xs = s * KXf, x2 = xs * xs;
  float pl = fmaf(x2, C7f, C5f);
  pl = fmaf(x2, pl, C3f);
  pl = fmaf(x2, pl, 1.0f);
  return __expf((CAPf * xs) * pl);
}
__device__ __forceinline__ float clip1(float e, float c1) {
  return fminf(fmaxf(fmaf(e, c1, -0.01f), 0.f), 1.f);
}

// ---- prep: split K and V into bf16 hi/lo arrays ----
__global__ __launch_bounds__(256)
void prep_split(const float* __restrict__ k, const float* __restrict__ v) {
  size_t i = (size_t)blockIdx.x * 256 + threadIdx.x;   // one float4
  if (i >= KVELEMS / 4) return;
  uint2 hi, lo;
  float4 kv = reinterpret_cast<const float4*>(k)[i];
  split4(kv, hi, lo);
  reinterpret_cast<uint2*>(gKH)[i] = hi;
  reinterpret_cast<uint2*>(gKL)[i] = lo;
  float4 vv = reinterpret_cast<const float4*>(v)[i];
  split4(vv, hi, lo);
  reinterpret_cast<uint2*>(gVH)[i] = hi;
  reinterpret_cast<uint2*>(gVL)[i] = lo;
}

// stage one 64-row K/V tile (hi+lo) into the single stage buffer (128 threads)
__device__ __forceinline__ void stage_tile(uint32_t sb, int tid, int jb, int kend,
                                           const __nv_bfloat16* hb, const __nv_bfloat16* lb) {
#pragma unroll
  for (int it = 0; it < 8; ++it) {
    int m = tid + 128 * it;                  // 1024 chunks = 64 rows x 16
    int r = m >> 4, c8 = m & 15, j = jb + r;
    uint32_t sz = (j < kend) ? 16u : 0u;
    size_t roff = (size_t)j * (HKVn * Dn) + 8 * c8;
    uint32_t doff = (uint32_t)(r * PQn) * 2 + 16 * c8;
    CPA16(sb + O_KH + doff, hb + roff, sz);
    CPA16(sb + O_KL + doff, lb + roff, sz);
  }
  CPA_COMMIT();
}

__global__ __launch_bounds__(128, 4)
void swa_mma(const float* __restrict__ q, float* __restrict__ out) {
  extern __shared__ char sm[];
  const uint32_t sb = s2u(sm);
  float* sums = reinterpret_cast<float*>(sm + O_SUMS);

  const int tid = threadIdx.x, w = tid >> 5, lane = tid & 31;
  const int mh = w & 1, nb = w >> 1;          // warp -> (m-half, n-half)
  const int quad = lane >> 2, c2 = (lane & 3) * 2;
  const int r0 = 16 * mh + quad, r1 = r0 + 8; // rows: same q-pos, adjacent heads
  const int qb = blockIdx.x, kvh = blockIdx.y, b = blockIdx.z;
  const int qs8 = qb * QPn;
  const int lo = (qs8 > WINn) ? (qs8 - WINn) : 0;
  const int kend = qs8 + QPn;                 // exclusive kv bound
  const int nt = (kend - lo + KTn - 1) >> 6;  // 64-row tiles
  const int cta = (b * HKVn + kvh) * NQBn + qb;
  float* __restrict__ strip = g_strip + (size_t)cta * (QTn * SPn);

  // ---- init sums + load/split Q (32 rows = 4 heads x 8 qpos, 128 d) ----
  if (tid < QTn) sums[tid] = 0.f;
  for (int m = tid; m < QTn * 32; m += 128) {
    int r = m >> 5, d4 = m & 31;
    const float* qp = q + (((size_t)(b * SQn + qs8 + (r & 7)) * HQn) + kvh * 4 + (r >> 3)) * Dn;
    float4 vv = *reinterpret_cast<const float4*>(qp + 4 * d4);
    uint2 hi, lo2;
    split4(vv, hi, lo2);
    uint32_t off = (uint32_t)(r * PQn + 4 * d4) * 2;
    *reinterpret_cast<uint2*>(sm + O_QH + off) = hi;
    *reinterpret_cast<uint2*>(sm + O_QL + off) = lo2;
  }

  const size_t kvbase = (size_t)b * SQn * HKVn * Dn + (size_t)kvh * Dn;
  const __nv_bfloat16* khb = gKH + kvbase;
  const __nv_bfloat16* klb = gKL + kvbase;
  const __nv_bfloat16* vhb = gVH + kvbase;
  const __nv_bfloat16* vlb = gVL + kvbase;

  // ldmatrix lane offsets
  const int aRow = 16 * mh + (lane & 7) + 8 * ((lane >> 3) & 1);
  const int aColB = 8 * ((lane >> 4) & 1);
  const int kRow = (lane & 7) + 8 * ((lane >> 4) & 1);
  const int kColB = 8 * ((lane >> 3) & 1);
  const int vRow = (lane & 7) + 8 * ((lane >> 3) & 1);
  const int vColB = 8 * ((lane >> 4) & 1);

  // ======================= QK phase (serial staging, warp m16 x n32) ==========
  float ssum0 = 0.f, ssum1 = 0.f;
  const int i0 = qs8 + quad;                  // q position for BOTH r0 and r1
  stage_tile(sb, tid, lo, kend, khb, klb);
  for (int t = 0; t < nt; ++t) {
    CPA_WAIT0();
    __syncthreads();            // K tile t ready for all warps
    const int jb = lo + t * KTn;

    float acc[4][4] = {};
#pragma unroll
    for (int ks = 0; ks < 8; ++ks) {
      uint32_t ah[4], al[4], bh[4], bl[4];
      uint32_t aoff = (uint32_t)(aRow * PQn + 16 * ks + aColB) * 2;
      ldsm4(sb + O_QH + aoff, ah);
      ldsm4(sb + O_QL + aoff, al);
#pragma unroll
      for (int p = 0; p < 2; ++p) {
        uint32_t boff = (uint32_t)((32 * nb + 16 * p + kRow) * PQn + 16 * ks + kColB) * 2;
        ldsm4(sb + O_KH + boff, bh);
        ldsm4(sb + O_KL + boff, bl);
        mma16816(acc[2 * p], ah, bh[0], bh[1]);
        mma16816(acc[2 * p], ah, bl[0], bl[1]);
        mma16816(acc[2 * p], al, bh[0], bh[1]);
        mma16816(acc[2 * p + 1], ah, bh[2], bh[3]);
        mma16816(acc[2 * p + 1], ah, bl[2], bl[3]);
        mma16816(acc[2 * p + 1], al, bh[2], bh[3]);
      }
    }
    __syncthreads();            // all warps done reading K tile t
    if (t + 1 < nt) stage_tile(sb, tid, jb + KTn, kend, khb, klb);

    // epilogue: cap/exp/mask -> permuted strip (float4) + register sums
#pragma unroll
    for (int p = 0; p < 2; ++p) {
      const int base = 32 * nb + 16 * p;
      const int jg0 = jb + base + c2;       // cols of acc[2p]
      const int jg8 = jg0 + 8;              // cols of acc[2p+1]
      float e00 = (jg0 >= i0 - WINn && jg0 <= i0) ? capexp(acc[2 * p][0]) : 0.f;
      float e01 = (jg0 + 1 >= i0 - WINn && jg0 + 1 <= i0) ? capexp(acc[2 * p][1]) : 0.f;
      float e02 = (jg8 >= i0 - WINn && jg8 <= i0) ? capexp(acc[2 * p + 1][0]) : 0.f;
      float e03 = (jg8 + 1 >= i0 - WINn && jg8 + 1 <= i0) ? capexp(acc[2 * p + 1][1]) : 0.f;
      float e10 = (jg0 >= i0 - WINn && jg0 <= i0) ? capexp(acc[2 * p][2]) : 0.f;
      float e11 = (jg0 + 1 >= i0 - WINn && jg0 + 1 <= i0) ? capexp(acc[2 * p][3]) : 0.f;
      float e12 = (jg8 >= i0 - WINn && jg8 <= i0) ? capexp(acc[2 * p + 1][2]) : 0.f;
      float e13 = (jg8 + 1 >= i0 - WINn && jg8 + 1 <= i0) ? capexp(acc[2 * p + 1][3]) : 0.f;
      ssum0 += (e00 + e01) + (e02 + e03);
      ssum1 += (e10 + e11) + (e12 + e13);
      const int ph = t * KTn + 16 * (2 * nb + p) + 2 * c2;
      __stcg(reinterpret_cast<float4*>(&strip[r0 * SPn + ph]), make_float4(e00, e01, e02, e03));
      __stcg(reinterpret_cast<float4*>(&strip[r1 * SPn + ph]), make_float4(e10, e11, e12, e13));
    }
  }

  // ---- row sums: 4-lane shfl reduce, one atomic per row ----
  ssum0 += __shfl_xor_sync(0xffffffffu, ssum0, 1);
  ssum0 += __shfl_xor_sync(0xffffffffu, ssum0, 2);
  ssum1 += __shfl_xor_sync(0xffffffffu, ssum1, 1);
  ssum1 += __shfl_xor_sync(0xffffffffu, ssum1, 2);
  if ((lane & 3) == 0) {
    atomicAdd(&sums[r0], ssum0);
    atomicAdd(&sums[r1], ssum1);
  }
  stage_tile(sb, tid, lo, kend, vhb, vlb);   // V tile 0 overlaps sums settling
  __syncthreads();              // sums ready

  // ======================= PV phase (serial staging, warp m16 x d64) ==========
  const float c1a = 1.02f / sums[r0], c1b = 1.02f / sums[r1];
  float oacc[8][4] = {};
  for (int t = 0; t < nt; ++t) {
    // prefetch this tile's P values (8x float4, L2) BEFORE the staging wait
    float4 P0v[4], P1v[4];
#pragma unroll
    for (int ks = 0; ks < 4; ++ks) {
      const int ph = t * KTn + 16 * ks + 2 * c2;
      P0v[ks] = __ldcg(reinterpret_cast<const float4*>(&strip[r0 * SPn + ph]));
      P1v[ks] = __ldcg(reinterpret_cast<const float4*>(&strip[r1 * SPn + ph]));
    }
    CPA_WAIT0();
    __syncthreads();            // V tile t ready

#pragma unroll
    for (int ks = 0; ks < 4; ++ks) {          // 4 x 16 kv rows per 64-tile
      float a00 = clip1(P0v[ks].x, c1a), a01 = clip1(P0v[ks].y, c1a);
      float a02 = clip1(P0v[ks].z, c1a), a03 = clip1(P0v[ks].w, c1a);
      float a10 = clip1(P1v[ks].x, c1b), a11 = clip1(P1v[ks].y, c1b);
      float a12 = clip1(P1v[ks].z, c1b), a13 = clip1(P1v[ks].w, c1b);
      uint32_t ah[4], al[4];
      split2(a00, a01, ah[0], al[0]);
      split2(a10, a11, ah[1], al[1]);
      split2(a02, a03, ah[2], al[2]);
      split2(a12, a13, ah[3], al[3]);
#pragma unroll
      for (int vd = 0; vd < 4; ++vd) {        // 4 x 16 d-cols -> d64 per warp
        uint32_t bh[4], bl[4];
        uint32_t boff = (uint32_t)((16 * ks + vRow) * PQn + 64 * nb + 16 * vd + vColB) * 2;
        ldsm4t(sb + O_KH + boff, bh);
        ldsm4t(sb + O_KL + boff, bl);
        mma16816(oacc[2 * vd], ah, bh[0], bh[1]);
        mma16816(oacc[2 * vd], ah, bl[0], bl[1]);
        mma16816(oacc[2 * vd], al, bh[0], bh[1]);
        mma16816(oacc[2 * vd + 1], ah, bh[2], bh[3]);
        mma16816(oacc[2 * vd + 1], ah, bl[2], bl[3]);
        mma16816(oacc[2 * vd + 1], al, bh[2], bh[3]);
      }
    }
    __syncthreads();            // all warps done reading V tile t
    if (t + 1 < nt) stage_tile(sb, tid, lo + (t + 1) * KTn, kend, vhb, vlb);
  }

  // ---- stage output through smem (reuse stage buffer), coalesced store ----
  float* ostage = reinterpret_cast<float*>(sm + O_KH);   // 32 x 132 f32
#pragma unroll
  for (int j4 = 0; j4 < 8; ++j4) {
    const int cb = 64 * nb + 8 * j4 + c2;
    *reinterpret_cast<float2*>(&ostage[r0 * 132 + cb]) = make_float2(oacc[j4][0], oacc[j4][1]);
    *reinterpret_cast<float2*>(&ostage[r1 * 132 + cb]) = make_float2(oacc[j4][2], oacc[j4][3]);
  }
  __syncthreads();
  for (int m = tid; m < QTn * 32; m += 128) {
    int r = m >> 5, d4 = m & 31;
    float* op = out + (((size_t)(b * SQn + qs8 + (r & 7)) * HQn) + kvh * 4 + (r >> 3)) * Dn;
    *reinterpret_cast<float4*>(op + 4 * d4) =
        *reinterpret_cast<const float4*>(&ostage[r * 132 + 4 * d4]);
  }
}

extern "C" void kernel_launch(void* const* d_in, const int* in_sizes, int n_in,
                              void* d_out, int out_size) {
  (void)in_sizes; (void)n_in; (void)out_size;
  const float* q = (const float*)d_in[0];
  const float* k = (const float*)d_in[1];
  const float* v = (const float*)d_in[2];
  float* out = (float*)d_out;
  cudaFuncSetAttribute(swa_mma, cudaFuncAttributeMaxDynamicSharedMemorySize, SMEM_SZ);
  prep_split<<<(int)((KVELEMS / 4 + 255) / 256), 256>>>(k, v);
  dim3 grid(NQBn, HKVn, 2);
  swa_mma<<<grid, 128, SMEM_SZ>>>(q, out);
}